// round 15
// baseline (speedup 1.0000x reference)
#include <cuda_runtime.h>
#include <cuda_bf16.h>
#include <cstdint>

constexpr int NTOK = 8192;
constexpr int DMOD = 512;

__device__ __nv_bfloat16 g_xb[NTOK * DMOD];
__device__ __nv_bfloat16 g_w0[DMOD * DMOD];
__device__ __nv_bfloat16 g_w1[DMOD * DMOD];
__device__ __nv_bfloat16 g_w2[DMOD * DMOD];
__device__ __nv_bfloat16 g_w3[DMOD * DMOD];
__device__ __nv_bfloat16 g_qb[NTOK * DMOD];
__device__ __nv_bfloat16 g_kb[NTOK * DMOD];
__device__ __nv_bfloat16 g_vb[NTOK * DMOD];
__device__ __nv_bfloat16 g_ab[NTOK * DMOD];
__device__ float g_cls[NTOK];
__device__ float g_Z0;

// attn2 smem: Q[0,32K) E 2x32K [32K,96K) K 2x32K [96K,160K) V 2x32K [160K,224K) srow[+1K) Zb[+128)
constexpr int EOFF = 32768;
constexpr int KOFF = 98304;
constexpr int VOFF = 163840;
constexpr int ROFF = 229376;
constexpr int ZOFF = 230400;
constexpr int SM_TOTAL = 230528;

__device__ __forceinline__ void ldm4(uint32_t &r0, uint32_t &r1, uint32_t &r2, uint32_t &r3, uint32_t ad)
{
    asm volatile("ldmatrix.sync.aligned.m8n8.x4.shared.b16 {%0,%1,%2,%3},[%4];"
                 : "=r"(r0), "=r"(r1), "=r"(r2), "=r"(r3) : "r"(ad));
}
__device__ __forceinline__ void ldm4t(uint32_t &r0, uint32_t &r1, uint32_t &r2, uint32_t &r3, uint32_t ad)
{
    asm volatile("ldmatrix.sync.aligned.m8n8.x4.trans.shared.b16 {%0,%1,%2,%3},[%4];"
                 : "=r"(r0), "=r"(r1), "=r"(r2), "=r"(r3) : "r"(ad));
}
__device__ __forceinline__ void mmab(float &c0, float &c1, float &c2, float &c3,
                                     uint32_t a0, uint32_t a1, uint32_t a2, uint32_t a3,
                                     uint32_t b0, uint32_t b1)
{
    asm volatile("mma.sync.aligned.m16n8k16.row.col.f32.bf16.bf16.f32 "
                 "{%0,%1,%2,%3},{%4,%5,%6,%7},{%8,%9},{%0,%1,%2,%3};"
                 : "+f"(c0), "+f"(c1), "+f"(c2), "+f"(c3)
                 : "r"(a0), "r"(a1), "r"(a2), "r"(a3), "r"(b0), "r"(b1));
}
__device__ __forceinline__ void cpa16(uint32_t s, const void* g)
{
    asm volatile("cp.async.cg.shared.global [%0],[%1],16;" :: "r"(s), "l"(g));
}
__device__ __forceinline__ void cpcommit() { asm volatile("cp.async.commit_group;"); }
__device__ __forceinline__ void cpwait0()  { asm volatile("cp.async.wait_group 0;"); }
__device__ __forceinline__ void barQK()    { asm volatile("bar.sync 1, 256;" ::: "memory"); }
__device__ __forceinline__ void barPV()    { asm volatile("bar.sync 2, 256;" ::: "memory"); }

// K stage: 256 keys x 64 d (32KB), rows 128B, swizzled; 256 threads (t = 0..255)
__device__ __forceinline__ void stageK(uint32_t buf, int c, int kh, int dq, int t)
{
#pragma unroll
    for (int i = 0; i < 8; i++) {
        int idx = i * 256 + t;
        int row = idx >> 3;
        int c16 = idx & 7;
        cpa16(buf + (uint32_t)(row * 128 + ((c16 ^ (row & 7)) << 4)),
              (const char*)(g_kb + (size_t)(c * 512 + kh * 256 + row) * DMOD) + dq * 128 + c16 * 16);
    }
}
// V stage: 32 keys x 512 d (32KB), rows 1024B, swizzled; 256 threads
__device__ __forceinline__ void stageV(uint32_t buf, int c, int s, int t)
{
#pragma unroll
    for (int i = 0; i < 8; i++) {
        int idx = i * 256 + t;
        int row = idx >> 6;
        int c16 = idx & 63;
        cpa16(buf + (uint32_t)(row * 1024 + ((c16 ^ (row & 7)) << 4)),
              (const char*)(g_vb + (size_t)(c * 512 + s * 32 + row) * DMOD) + c16 * 16);
    }
}

__global__ __launch_bounds__(512)
void attn2()
{
    extern __shared__ char sm[];
    uint32_t sb = (uint32_t)__cvta_generic_to_shared(sm);
    float* srow = (float*)(sm + ROFF);
    float* Zb   = (float*)(sm + ZOFF);

    const int tid  = threadIdx.x;
    const int lane = tid & 31;
    const int r8   = lane & 7;
    const int jj   = lane >> 3;
    const int gid  = lane >> 2;
    const int tig  = lane & 3;
    const int q0   = blockIdx.x << 5;
    const float SC = 0.044194173824159216f;  // 1/sqrt(512)

    if (tid < 32) Zb[tid] = 0.f;

    // Q tile (32x512 bf16) -> smem swizzled, rows 1024B (all 512 threads)
    const char* qg = (const char*)(g_qb + (size_t)q0 * DMOD);
#pragma unroll
    for (int i = 0; i < 4; i++) {
        int idx = i * 512 + tid;
        int row = idx >> 6;
        int c16 = idx & 63;
        *(uint4*)(sm + row * 1024 + ((c16 ^ (row & 7)) << 4)) =
            *(const uint4*)(qg + (size_t)row * 1024 + (size_t)c16 * 16);
    }
    __syncthreads();

    const bool isQK = (tid < 256);
    const int wq = tid >> 5;        // 0..7 for QK group
    const int wv = (tid >> 5) - 8;  // 0..7 for PV group

    // QK frags
    const int rA0 = r8 + ((jj & 1) << 3);
    const int rA1 = rA0 + 16;
    const int cA8 = jj >> 1;
    const int rB0 = wq * 32 + r8 + ((jj >> 1) << 3);   // within 256-key stage
    const int rB1 = rB0 + 16;
    const int cB8 = jj & 1;
    // PV frags
    const int rP  = r8 + ((jj & 1) << 3);
    const int cP8 = jj >> 1;

    float O[2][8][4];
#pragma unroll
    for (int x1 = 0; x1 < 2; x1++)
#pragma unroll
        for (int x2 = 0; x2 < 8; x2++)
#pragma unroll
            for (int x3 = 0; x3 < 4; x3++) { O[x1][x2][x3] = 0.f; }

    int pb = 0;
    if (isQK) stageK(sb + KOFF, 0, 0, 0, tid);
    else      stageV(sb + VOFF, 0, 0, tid - 256);
    cpcommit();

    for (int ph = 0; ph <= 16; ph++) {
        if (isQK) {
            if (ph < 16) {
                uint32_t eb = sb + EOFF + (uint32_t)(ph & 1) * 32768;
                // 2 key-halves; S lives per half only (32 regs)
                for (int kh = 0; kh < 2; kh++) {
                    float S2[2][4][4];
#pragma unroll
                    for (int mt = 0; mt < 2; mt++)
#pragma unroll
                        for (int n8 = 0; n8 < 4; n8++)
#pragma unroll
                            for (int u = 0; u < 4; u++) { S2[mt][n8][u] = 0.f; }

                    for (int dq = 0; dq < 8; dq++) {
                        cpwait0();
                        barQK();
                        int nst = kh * 8 + dq + 1;
                        uint32_t nb = sb + KOFF + (uint32_t)((pb ^ 1) << 15);
                        if (nst < 16)       stageK(nb, ph, nst >> 3, nst & 7, tid);
                        else if (ph + 1 < 16) stageK(nb, ph + 1, 0, 0, tid);
                        cpcommit();
                        uint32_t stg = sb + KOFF + (uint32_t)(pb << 15);
#pragma unroll
                        for (int ks = 0; ks < 4; ks++) {
                            int cq = dq * 8 + ks * 2 + cA8;   // Q c16 index 0..63
                            uint32_t a00, a01, a02, a03, a10, a11, a12, a13;
                            ldm4(a00, a01, a02, a03, sb + (uint32_t)(rA0 * 1024 + ((cq ^ (rA0 & 7)) << 4)));
                            ldm4(a10, a11, a12, a13, sb + (uint32_t)(rA1 * 1024 + ((cq ^ (rA1 & 7)) << 4)));
                            int ck = ks * 2 + cB8;            // stage c16 index 0..7
                            uint32_t b0, b1, b2, b3;
                            ldm4(b0, b1, b2, b3, stg + (uint32_t)(rB0 * 128 + ((ck ^ (rB0 & 7)) << 4)));
                            mmab(S2[0][0][0], S2[0][0][1], S2[0][0][2], S2[0][0][3], a00, a01, a02, a03, b0, b1);
                            mmab(S2[0][1][0], S2[0][1][1], S2[0][1][2], S2[0][1][3], a00, a01, a02, a03, b2, b3);
                            mmab(S2[1][0][0], S2[1][0][1], S2[1][0][2], S2[1][0][3], a10, a11, a12, a13, b0, b1);
                            mmab(S2[1][1][0], S2[1][1][1], S2[1][1][2], S2[1][1][3], a10, a11, a12, a13, b2, b3);
                            ldm4(b0, b1, b2, b3, stg + (uint32_t)(rB1 * 128 + ((ck ^ (rB1 & 7)) << 4)));
                            mmab(S2[0][2][0], S2[0][2][1], S2[0][2][2], S2[0][2][3], a00, a01, a02, a03, b0, b1);
                            mmab(S2[0][3][0], S2[0][3][1], S2[0][3][2], S2[0][3][3], a00, a01, a02, a03, b2, b3);
                            mmab(S2[1][2][0], S2[1][2][1], S2[1][2][2], S2[1][2][3], a10, a11, a12, a13, b0, b1);
                            mmab(S2[1][3][0], S2[1][3][1], S2[1][3][2], S2[1][3][3], a10, a11, a12, a13, b2, b3);
                        }
                        pb ^= 1;
                    }
                    // E1 = exp(S*SC) -> E buffer, per-warp row sums
#pragma unroll
                    for (int mt = 0; mt < 2; mt++) {
                        float pr0 = 0.f, pr1 = 0.f;
                        int rw0 = mt * 16 + gid;
                        int rw1 = rw0 + 8;
#pragma unroll
                        for (int n8 = 0; n8 < 4; n8++) {
                            float e0 = __expf(S2[mt][n8][0] * SC), e1 = __expf(S2[mt][n8][1] * SC);
                            float e2 = __expf(S2[mt][n8][2] * SC), e3 = __expf(S2[mt][n8][3] * SC);
                            pr0 += e0 + e1; pr1 += e2 + e3;
                            int key = kh * 256 + wq * 32 + n8 * 8 + tig * 2;
                            *(__nv_bfloat162*)(sm + (eb - sb) + rw0 * 1024 + (((key >> 3) ^ (rw0 & 7)) << 4) + ((key & 7) << 1)) = __floats2bfloat162_rn(e0, e1);
                            *(__nv_bfloat162*)(sm + (eb - sb) + rw1 * 1024 + (((key >> 3) ^ (rw1 & 7)) << 4) + ((key & 7) << 1)) = __floats2bfloat162_rn(e2, e3);
                        }
                        pr0 += __shfl_xor_sync(0xffffffffu, pr0, 1);
                        pr0 += __shfl_xor_sync(0xffffffffu, pr0, 2);
                        pr1 += __shfl_xor_sync(0xffffffffu, pr1, 1);
                        pr1 += __shfl_xor_sync(0xffffffffu, pr1, 2);
                        if (tig == 0) {
                            if (kh == 0) { srow[wq * 32 + rw0] = pr0;  srow[wq * 32 + rw1] = pr1; }
                            else         { srow[wq * 32 + rw0] += pr0; srow[wq * 32 + rw1] += pr1; }
                        }
                    }
                }
                barQK();
                // chunk softmax -> E2 in place, Z accum, cls (QK group, 256 threads)
                {
                    int row = tid >> 3;
                    int seg = tid & 7;
                    float s = 0.f;
#pragma unroll
                    for (int w = 0; w < 8; w++) { s += srow[w * 32 + row]; }
                    float rinv = 1.f / s;
                    float z = 0.f;
#pragma unroll
                    for (int i = 0; i < 8; i++) {
                        int c16 = seg * 8 + i;
                        uint32_t* p = (uint32_t*)(sm + (eb - sb) + row * 1024 + ((c16 ^ (row & 7)) << 4));
#pragma unroll
                        for (int qq = 0; qq < 4; qq++) {
                            float2 fv = __bfloat1622float2(*(__nv_bfloat162*)(p + qq));
                            float u0 = __expf(fv.x * rinv);
                            float u1 = __expf(fv.y * rinv);
                            z += u0 + u1;
                            *(__nv_bfloat162*)(p + qq) = __floats2bfloat162_rn(u0, u1);
                            if (blockIdx.x == 0 && row == 0) {
                                int col = c16 * 8 + qq * 2;
                                g_cls[ph * 512 + col]     = u0;
                                g_cls[ph * 512 + col + 1] = u1;
                            }
                        }
                    }
                    z += __shfl_xor_sync(0xffffffffu, z, 1);
                    z += __shfl_xor_sync(0xffffffffu, z, 2);
                    z += __shfl_xor_sync(0xffffffffu, z, 4);
                    if (seg == 0) Zb[row] += z;
                }
            }
        } else {
            if (ph >= 1) {
                const int c = ph - 1;
                const int t = tid - 256;
                uint32_t ebase = sb + EOFF + (uint32_t)(c & 1) * 32768;
                for (int st = 0; st < 16; st++) {
                    cpwait0();
                    barPV();
                    int nst = st + 1;
                    uint32_t nb = sb + VOFF + (uint32_t)((pb ^ 1) << 15);
                    if (nst < 16)       stageV(nb, c, nst, t);
                    else if (c + 1 < 16) stageV(nb, c + 1, 0, t);
                    cpcommit();
                    uint32_t stg = sb + VOFF + (uint32_t)(pb << 15);
#pragma unroll
                    for (int ks = 0; ks < 2; ks++) {
                        uint32_t a00, a01, a02, a03, a10, a11, a12, a13;
                        int ce  = st * 4 + ks * 2 + cP8;   // E c16 index 0..63
                        int ra1 = 16 + rP;
                        ldm4(a00, a01, a02, a03, ebase + (uint32_t)(rP  * 1024 + ((ce ^ (rP  & 7)) << 4)));
                        ldm4(a10, a11, a12, a13, ebase + (uint32_t)(ra1 * 1024 + ((ce ^ (ra1 & 7)) << 4)));
                        int rv = ks * 16 + rP;
#pragma unroll
                        for (int nt2 = 0; nt2 < 4; nt2++) {
                            uint32_t b0, b1, b2, b3;
                            int cv = wv * 8 + nt2 * 2 + cP8;
                            ldm4t(b0, b1, b2, b3, stg + (uint32_t)(rv * 1024 + ((cv ^ (rv & 7)) << 4)));
                            mmab(O[0][2*nt2  ][0], O[0][2*nt2  ][1], O[0][2*nt2  ][2], O[0][2*nt2  ][3], a00, a01, a02, a03, b0, b1);
                            mmab(O[0][2*nt2+1][0], O[0][2*nt2+1][1], O[0][2*nt2+1][2], O[0][2*nt2+1][3], a00, a01, a02, a03, b2, b3);
                            mmab(O[1][2*nt2  ][0], O[1][2*nt2  ][1], O[1][2*nt2  ][2], O[1][2*nt2  ][3], a10, a11, a12, a13, b0, b1);
                            mmab(O[1][2*nt2+1][0], O[1][2*nt2+1][1], O[1][2*nt2+1][2], O[1][2*nt2+1][3], a10, a11, a12, a13, b2, b3);
                        }
                    }
                    pb ^= 1;
                }
            }
        }
        __syncthreads();
    }

    // normalize + store bf16 (PV group)
    if (!isQK) {
#pragma unroll
        for (int mt = 0; mt < 2; mt++) {
            int r0 = mt * 16 + gid;
            float z0 = 1.f / Zb[r0];
            float z1 = 1.f / Zb[r0 + 8];
#pragma unroll
            for (int nt = 0; nt < 8; nt++) {
                int col = wv * 64 + nt * 8 + tig * 2;
                *(__nv_bfloat162*)&g_ab[(size_t)(q0 + r0) * DMOD + col]     = __floats2bfloat162_rn(O[mt][nt][0] * z0, O[mt][nt][1] * z0);
                *(__nv_bfloat162*)&g_ab[(size_t)(q0 + r0 + 8) * DMOD + col] = __floats2bfloat162_rn(O[mt][nt][2] * z1, O[mt][nt][3] * z1);
            }
        }
    }
    if (blockIdx.x == 0 && tid == 0) g_Z0 = Zb[0];
}

// ---------------- bf16 tensor-core QKV projection GEMM ----------------
__global__ __launch_bounds__(256)
void gemm_qkv(const __nv_bfloat16* __restrict__ A,
              const __nv_bfloat16* __restrict__ Wa, const __nv_bfloat16* __restrict__ Wb2, const __nv_bfloat16* __restrict__ Wc,
              const float* __restrict__ ba, const float* __restrict__ bb2, const float* __restrict__ bc,
              __nv_bfloat16* __restrict__ oa, __nv_bfloat16* __restrict__ ob, __nv_bfloat16* __restrict__ oc)
{
    extern __shared__ char smg[];
    uint32_t sb = (uint32_t)__cvta_generic_to_shared(smg);

    const __nv_bfloat16* W;
    const float* bias;
    __nv_bfloat16* out;
    if (blockIdx.z == 0)      { W = Wa;  bias = ba;  out = oa; }
    else if (blockIdx.z == 1) { W = Wb2; bias = bb2; out = ob; }
    else                      { W = Wc;  bias = bc;  out = oc; }

    const int tid  = threadIdx.x;
    const int wd   = tid >> 5;
    const int lane = tid & 31;
    const int r8   = lane & 7;
    const int jj   = lane >> 3;
    const int gid  = lane >> 2;
    const int tig  = lane & 3;
    const int wm   = wd >> 2;
    const int wn   = wd & 3;
    const int bm   = blockIdx.x * 128;
    const int bn   = blockIdx.y * 128;
    const int rP   = r8 + ((jj & 1) << 3);
    const int cP8  = jj >> 1;

    float acc[4][4][4];
#pragma unroll
    for (int mt = 0; mt < 4; mt++)
#pragma unroll
        for (int nt = 0; nt < 4; nt++)
#pragma unroll
            for (int q2 = 0; q2 < 4; q2++) { acc[mt][nt][q2] = 0.f; }

#pragma unroll
    for (int i = 0; i < 4; i++) {
        int idx = i * 256 + tid;
        int row = idx >> 3;
        int c16 = idx & 7;
        cpa16(sb + (uint32_t)(row * 128 + ((c16 ^ (row & 7)) << 4)),
              (const char*)(A + (size_t)(bm + row) * DMOD) + (size_t)c16 * 16);
    }
#pragma unroll
    for (int i = 0; i < 4; i++) {
        int idx = i * 256 + tid;
        int k = idx >> 4;
        int c16 = idx & 15;
        cpa16(sb + (uint32_t)(32768 + k * 256 + ((c16 ^ (k & 7)) << 4)),
              (const char*)(W + (size_t)k * DMOD + bn) + (size_t)c16 * 16);
    }
    cpcommit();

    for (int s = 0; s < 8; s++) {
        cpwait0();
        __syncthreads();
        if (s < 7) {
            int ns = s + 1;
            uint32_t ab = sb + (uint32_t)((ns & 1) * 16384);
            uint32_t wb = sb + (uint32_t)(32768 + (ns & 1) * 16384);
#pragma unroll
            for (int i = 0; i < 4; i++) {
                int idx = i * 256 + tid;
                int row = idx >> 3;
                int c16 = idx & 7;
                cpa16(ab + (uint32_t)(row * 128 + ((c16 ^ (row & 7)) << 4)),
                      (const char*)(A + (size_t)(bm + row) * DMOD + (size_t)ns * 64) + (size_t)c16 * 16);
            }
#pragma unroll
            for (int i = 0; i < 4; i++) {
                int idx = i * 256 + tid;
                int k = idx >> 4;
                int c16 = idx & 15;
                cpa16(wb + (uint32_t)(k * 256 + ((c16 ^ (k & 7)) << 4)),
                      (const char*)(W + (size_t)(ns * 64 + k) * DMOD + bn) + (size_t)c16 * 16);
            }
            cpcommit();
        }
        uint32_t sa = sb + (uint32_t)((s & 1) * 16384);
        uint32_t sw = sb + (uint32_t)(32768 + (s & 1) * 16384);
#pragma unroll
        for (int ks = 0; ks < 4; ks++) {
            uint32_t am[4][4];
            int ck = ks * 2 + cP8;
#pragma unroll
            for (int mt = 0; mt < 4; mt++) {
                int rowA = wm * 64 + mt * 16 + rP;
                ldm4(am[mt][0], am[mt][1], am[mt][2], am[mt][3], sa + (uint32_t)(rowA * 128 + ((ck ^ (rowA & 7)) << 4)));
            }
#pragma unroll
            for (int nt2 = 0; nt2 < 2; nt2++) {
                uint32_t b0, b1, b2, b3;
                int rv = ks * 16 + rP;
                int cv = wn * 4 + nt2 * 2 + cP8;
                ldm4t(b0, b1, b2, b3, sw + (uint32_t)(rv * 256 + ((cv ^ (rv & 7)) << 4)));
#pragma unroll
                for (int mt = 0; mt < 4; mt++) {
                    mmab(acc[mt][2*nt2  ][0], acc[mt][2*nt2  ][1], acc[mt][2*nt2  ][2], acc[mt][2*nt2  ][3], am[mt][0], am[mt][1], am[mt][2], am[mt][3], b0, b1);
                    mmab(acc[mt][2*nt2+1][0], acc[mt][2*nt2+1][1], acc[mt][2*nt2+1][2], acc[mt][2*nt2+1][3], am[mt][0], am[mt][1], am[mt][2], am[mt][3], b2, b3);
                }
            }
        }
    }

#pragma unroll
    for (int mt = 0; mt < 4; mt++) {
        int row0 = bm + wm * 64 + mt * 16 + gid;
        int row1 = row0 + 8;
#pragma unroll
        for (int nt = 0; nt < 4; nt++) {
            int col = bn + wn * 32 + nt * 8 + tig * 2;
            float bx = bias[col];
            float by = bias[col + 1];
            *(__nv_bfloat162*)&out[(size_t)row0 * DMOD + col] = __floats2bfloat162_rn(acc[mt][nt][0] + bx, acc[mt][nt][1] + by);
            *(__nv_bfloat162*)&out[(size_t)row1 * DMOD + col] = __floats2bfloat162_rn(acc[mt][nt][2] + bx, acc[mt][nt][3] + by);
        }
    }
}

// ------------- bf16 output projection GEMM: out = A@W + bias + resid (fp32) -------------
__global__ __launch_bounds__(256)
void gemm_out(const __nv_bfloat16* __restrict__ A, const __nv_bfloat16* __restrict__ W,
              const float* __restrict__ bias, const float* __restrict__ resid,
              float* __restrict__ out)
{
    extern __shared__ char smg[];
    uint32_t sb = (uint32_t)__cvta_generic_to_shared(smg);

    const int tid  = threadIdx.x;
    const int wd   = tid >> 5;
    const int lane = tid & 31;
    const int r8   = lane & 7;
    const int jj   = lane >> 3;
    const int gid  = lane >> 2;
    const int tig  = lane & 3;
    const int wm   = wd >> 2;
    const int wn   = wd & 3;
    const int bm   = blockIdx.x * 128;
    const int bn   = blockIdx.y * 128;
    const int rP   = r8 + ((jj & 1) << 3);
    const int cP8  = jj >> 1;

    float acc[4][4][4];
#pragma unroll
    for (int mt = 0; mt < 4; mt++)
#pragma unroll
        for (int nt = 0; nt < 4; nt++)
#pragma unroll
            for (int q2 = 0; q2 < 4; q2++) { acc[mt][nt][q2] = 0.f; }

#pragma unroll
    for (int i = 0; i < 4; i++) {
        int idx = i * 256 + tid;
        int row = idx >> 3;
        int c16 = idx & 7;
        cpa16(sb + (uint32_t)(row * 128 + ((c16 ^ (row & 7)) << 4)),
              (const char*)(A + (size_t)(bm + row) * DMOD) + (size_t)c16 * 16);
    }
#pragma unroll
    for (int i = 0; i < 4; i++) {
        int idx = i * 256 + tid;
        int k = idx >> 4;
        int c16 = idx & 15;
        cpa16(sb + (uint32_t)(32768 + k * 256 + ((c16 ^ (k & 7)) << 4)),
              (const char*)(W + (size_t)k * DMOD + bn) + (size_t)c16 * 16);
    }
    cpcommit();

    for (int s = 0; s < 8; s++) {
        cpwait0();
        __syncthreads();
        if (s < 7) {
            int ns = s + 1;
            uint32_t ab = sb + (uint32_t)((ns & 1) * 16384);
            uint32_t wb = sb + (uint32_t)(32768 + (ns & 1) * 16384);
#pragma unroll
            for (int i = 0; i < 4; i++) {
                int idx = i * 256 + tid;
                int row = idx >> 3;
                int c16 = idx & 7;
                cpa16(ab + (uint32_t)(row * 128 + ((c16 ^ (row & 7)) << 4)),
                      (const char*)(A + (size_t)(bm + row) * DMOD + (size_t)ns * 64) + (size_t)c16 * 16);
            }
#pragma unroll
            for (int i = 0; i < 4; i++) {
                int idx = i * 256 + tid;
                int k = idx >> 4;
                int c16 = idx & 15;
                cpa16(wb + (uint32_t)(k * 256 + ((c16 ^ (k & 7)) << 4)),
                      (const char*)(W + (size_t)(ns * 64 + k) * DMOD + bn) + (size_t)c16 * 16);
            }
            cpcommit();
        }
        uint32_t sa = sb + (uint32_t)((s & 1) * 16384);
        uint32_t sw = sb + (uint32_t)(32768 + (s & 1) * 16384);
#pragma unroll
        for (int ks = 0; ks < 4; ks++) {
            uint32_t am[4][4];
            int ck = ks * 2 + cP8;
#pragma unroll
            for (int mt = 0; mt < 4; mt++) {
                int rowA = wm * 64 + mt * 16 + rP;
                ldm4(am[mt][0], am[mt][1], am[mt][2], am[mt][3], sa + (uint32_t)(rowA * 128 + ((ck ^ (rowA & 7)) << 4)));
            }
#pragma unroll
            for (int nt2 = 0; nt2 < 2; nt2++) {
                uint32_t b0, b1, b2, b3;
                int rv = ks * 16 + rP;
                int cv = wn * 4 + nt2 * 2 + cP8;
                ldm4t(b0, b1, b2, b3, sw + (uint32_t)(rv * 256 + ((cv ^ (rv & 7)) << 4)));
#pragma unroll
                for (int mt = 0; mt < 4; mt++) {
                    mmab(acc[mt][2*nt2  ][0], acc[mt][2*nt2  ][1], acc[mt][2*nt2  ][2], acc[mt][2*nt2  ][3], am[mt][0], am[mt][1], am[mt][2], am[mt][3], b0, b1);
                    mmab(acc[mt][2*nt2+1][0], acc[mt][2*nt2+1][1], acc[mt][2*nt2+1][2], acc[mt][2*nt2+1][3], am[mt][0], am[mt][1], am[mt][2], am[mt][3], b2, b3);
                }
            }
        }
    }

#pragma unroll
    for (int mt = 0; mt < 4; mt++) {
        int row0 = bm + wm * 64 + mt * 16 + gid;
        int row1 = row0 + 8;
#pragma unroll
        for (int nt = 0; nt < 4; nt++) {
            int col = bn + wn * 32 + nt * 8 + tig * 2;
            float bx = bias[col];
            float by = bias[col + 1];
            float2 ra = *(const float2*)&resid[(size_t)row0 * DMOD + col];
            float2 rb = *(const float2*)&resid[(size_t)row1 * DMOD + col];
            float2 v0 = make_float2(acc[mt][nt][0] + bx + ra.x, acc[mt][nt][1] + by + ra.y);
            float2 v1 = make_float2(acc[mt][nt][2] + bx + rb.x, acc[mt][nt][3] + by + rb.y);
            *(float2*)&out[(size_t)row0 * DMOD + col] = v0;
            *(float2*)&out[(size_t)row1 * DMOD + col] = v1;
        }
    }
}

__global__ void convf2b(const float* __restrict__ s, __nv_bfloat16* __restrict__ d, int n4)
{
    int i = blockIdx.x * blockDim.x + threadIdx.x;
    if (i < n4) {
        float4 v = ((const float4*)s)[i];
        ((__nv_bfloat162*)d)[2 * i]     = __floats2bfloat162_rn(v.x, v.y);
        ((__nv_bfloat162*)d)[2 * i + 1] = __floats2bfloat162_rn(v.z, v.w);
    }
}

__global__ void convw4(const float* __restrict__ Wq, const float* __restrict__ Wk,
                       const float* __restrict__ Wv, const float* __restrict__ Wo)
{
    int i = blockIdx.x * blockDim.x + threadIdx.x;   // 0 .. 4*65536-1
    int w = i >> 16;
    int j = i & 65535;
    const float* s;
    __nv_bfloat16* d;
    if (w == 0)      { s = Wq; d = g_w0; }
    else if (w == 1) { s = Wk; d = g_w1; }
    else if (w == 2) { s = Wv; d = g_w2; }
    else             { s = Wo; d = g_w3; }
    float4 v = ((const float4*)s)[j];
    ((__nv_bfloat162*)d)[2 * j]     = __floats2bfloat162_rn(v.x, v.y);
    ((__nv_bfloat162*)d)[2 * j + 1] = __floats2bfloat162_rn(v.z, v.w);
}

__global__ void cls_kernel(float* __restrict__ out)
{
    int m = blockIdx.x * 256 + threadIdx.x;
    out[m] = g_cls[m] / g_Z0;
}

extern "C" void kernel_launch(void* const* d_in, const int* in_sizes, int n_in,
                              void* d_out, int out_size)
{
    const float* x  = (const float*)d_in[0];
    const float* Wq = (const float*)d_in[1];
    const float* bq = (const float*)d_in[2];
    const float* Wk = (const float*)d_in[3];
    const float* bk = (const float*)d_in[4];
    const float* Wv = (const float*)d_in[5];
    const float* bv = (const float*)d_in[6];
    const float* Wo = (const float*)d_in[7];
    const float* bo = (const float*)d_in[8];
    float* out = (float*)d_out;

    __nv_bfloat16 *xb = 0, *w0 = 0, *w1 = 0, *w2 = 0, *w3 = 0, *qb = 0, *kb = 0, *vb = 0, *ab = 0;
    cudaGetSymbolAddress((void**)&xb, g_xb);
    cudaGetSymbolAddress((void**)&w0, g_w0);
    cudaGetSymbolAddress((void**)&w1, g_w1);
    cudaGetSymbolAddress((void**)&w2, g_w2);
    cudaGetSymbolAddress((void**)&w3, g_w3);
    cudaGetSymbolAddress((void**)&qb, g_qb);
    cudaGetSymbolAddress((void**)&kb, g_kb);
    cudaGetSymbolAddress((void**)&vb, g_vb);
    cudaGetSymbolAddress((void**)&ab, g_ab);

    cudaFuncSetAttribute(attn2, cudaFuncAttributeMaxDynamicSharedMemorySize, SM_TOTAL);
    cudaFuncSetAttribute(gemm_qkv, cudaFuncAttributeMaxDynamicSharedMemorySize, 65536);
    cudaFuncSetAttribute(gemm_out, cudaFuncAttributeMaxDynamicSharedMemorySize, 65536);

    convf2b<<<4096, 256>>>(x, xb, NTOK * DMOD / 4);
    convw4<<<1024, 256>>>(Wq, Wk, Wv, Wo);

    dim3 gq(64, 4, 3);
    gemm_qkv<<<gq, 256, 65536>>>(xb, w0, w1, w2, bq, bk, bv, qb, kb, vb);

    attn2<<<256, 512, SM_TOTAL>>>();

    dim3 gg(64, 4);
    gemm_out<<<gg, 256, 65536>>>(ab, w3, bo, x, out);
    cls_kernel<<<32, 256>>>(out + (size_t)NTOK * DMOD);
}

// round 17
// speedup vs baseline: 1.8669x; 1.8669x over previous
#include <cuda_runtime.h>
#include <cuda_bf16.h>
#include <cstdint>

constexpr int NTOK = 8192;
constexpr int DMOD = 512;

__device__ __nv_bfloat16 g_xb[NTOK * DMOD];
__device__ __nv_bfloat16 g_w0[DMOD * DMOD];
__device__ __nv_bfloat16 g_w1[DMOD * DMOD];
__device__ __nv_bfloat16 g_w2[DMOD * DMOD];
__device__ __nv_bfloat16 g_w3[DMOD * DMOD];
__device__ __nv_bfloat16 g_qb[NTOK * DMOD];
__device__ __nv_bfloat16 g_kb[NTOK * DMOD];   // K in 64KB stage-block layout (16 chunks x 8 d-eighths)
__device__ __nv_bfloat16 g_vb[NTOK * DMOD];   // V in 64KB stage-block layout (16 chunks x 8 kv-64key)
__device__ __nv_bfloat16 g_ab[NTOK * DMOD];
__device__ float g_cls[NTOK];
__device__ float g_Z0;

// attn2 smem: Q[0,32K) E[32K,64K) stages 2x64K [64K,192K) srow[196608,+2K) Zb[198656,+128) mbar[198784,+16)
constexpr int EOFF = 32768;
constexpr int SOFF = 65536;
constexpr int ROFF = 196608;
constexpr int ZOFF = 198656;
constexpr int MOFF = 198784;
constexpr int SM_TOTAL = 198912;

__device__ __forceinline__ void ldm4(uint32_t &r0, uint32_t &r1, uint32_t &r2, uint32_t &r3, uint32_t ad)
{
    asm volatile("ldmatrix.sync.aligned.m8n8.x4.shared.b16 {%0,%1,%2,%3},[%4];"
                 : "=r"(r0), "=r"(r1), "=r"(r2), "=r"(r3) : "r"(ad));
}
__device__ __forceinline__ void ldm4t(uint32_t &r0, uint32_t &r1, uint32_t &r2, uint32_t &r3, uint32_t ad)
{
    asm volatile("ldmatrix.sync.aligned.m8n8.x4.trans.shared.b16 {%0,%1,%2,%3},[%4];"
                 : "=r"(r0), "=r"(r1), "=r"(r2), "=r"(r3) : "r"(ad));
}
__device__ __forceinline__ void mmab(float &c0, float &c1, float &c2, float &c3,
                                     uint32_t a0, uint32_t a1, uint32_t a2, uint32_t a3,
                                     uint32_t b0, uint32_t b1)
{
    asm volatile("mma.sync.aligned.m16n8k16.row.col.f32.bf16.bf16.f32 "
                 "{%0,%1,%2,%3},{%4,%5,%6,%7},{%8,%9},{%0,%1,%2,%3};"
                 : "+f"(c0), "+f"(c1), "+f"(c2), "+f"(c3)
                 : "r"(a0), "r"(a1), "r"(a2), "r"(a3), "r"(b0), "r"(b1));
}
__device__ __forceinline__ void cpa16(uint32_t s, const void* g)
{
    asm volatile("cp.async.cg.shared.global [%0],[%1],16;" :: "r"(s), "l"(g));
}
__device__ __forceinline__ void cpcommit() { asm volatile("cp.async.commit_group;"); }
__device__ __forceinline__ void cpwait0()  { asm volatile("cp.async.wait_group 0;"); }

// ---- mbarrier + bulk-copy (TMA-unit) helpers ----
__device__ __forceinline__ void mbar_init(uint32_t ad, uint32_t cnt)
{
    asm volatile("mbarrier.init.shared.b64 [%0], %1;" :: "r"(ad), "r"(cnt) : "memory");
}
__device__ __forceinline__ void mbar_expect(uint32_t ad, uint32_t bytes)
{
    asm volatile("mbarrier.arrive.expect_tx.shared.b64 _, [%0], %1;" :: "r"(ad), "r"(bytes) : "memory");
}
__device__ __forceinline__ void bulkld(uint32_t dst, const void* src, uint32_t bytes, uint32_t bar)
{
    asm volatile("cp.async.bulk.shared::cta.global.mbarrier::complete_tx::bytes [%0], [%1], %2, [%3];"
                 :: "r"(dst), "l"(src), "r"(bytes), "r"(bar) : "memory");
}
__device__ __forceinline__ void mbar_wait(uint32_t ad, uint32_t par)
{
    asm volatile(
        "{\n\t"
        ".reg .pred P;\n"
        "LAB_%=:\n\t"
        "mbarrier.try_wait.parity.acquire.cta.shared::cta.b64 P, [%0], %1, 0x989680;\n\t"
        "@!P bra LAB_%=;\n\t"
        "}"
        :: "r"(ad), "r"(par) : "memory");
}

// stage g (0..255): chunk c = g>>4; t = g&15. t<8 -> K d-eighth block, else V 64-key block.
__device__ __forceinline__ const char* stage_src(int g)
{
    int c = g >> 4;
    int t = g & 15;
    if (t < 8) return (const char*)g_kb + ((size_t)(c * 8 + t)) * 65536;
    return (const char*)g_vb + ((size_t)(c * 8 + (t - 8))) * 65536;
}

__global__ __launch_bounds__(512)
void attn2()
{
    extern __shared__ char sm[];
    uint32_t sb = (uint32_t)__cvta_generic_to_shared(sm);
    float* srow = (float*)(sm + ROFF);
    float* Zb   = (float*)(sm + ZOFF);
    const uint32_t mb = sb + MOFF;

    const int tid  = threadIdx.x;
    const int wd   = tid >> 5;     // 0..15
    const int lane = tid & 31;
    const int r8   = lane & 7;
    const int jj   = lane >> 3;
    const int gid  = lane >> 2;
    const int tig  = lane & 3;
    const int wn   = wd;
    const int q0   = blockIdx.x << 5;
    const float SC = 0.044194173824159216f;  // 1/sqrt(512)

    if (tid < 32) Zb[tid] = 0.f;
    srow[tid] = 0.f;

    // Q tile (32x512 bf16) -> smem swizzled, rows 1024B
    const char* qg = (const char*)(g_qb + (size_t)q0 * DMOD);
#pragma unroll
    for (int i = 0; i < 4; i++) {
        int idx = i * 512 + tid;
        int row = idx >> 6;
        int c16 = idx & 63;
        *(uint4*)(sm + row * 1024 + ((c16 ^ (row & 7)) << 4)) =
            *(const uint4*)(qg + (size_t)row * 1024 + (size_t)c16 * 16);
    }

    if (tid == 0) {
        mbar_init(mb, 1);
        mbar_init(mb + 8, 1);
    }
    __syncthreads();
    if (tid == 0) {
        mbar_expect(mb, 65536);
        bulkld(sb + SOFF, stage_src(0), 65536, mb);
    }

    const int rA0 = r8 + ((jj & 1) << 3);
    const int rA1 = rA0 + 16;
    const int cA8 = jj >> 1;
    const int rB0 = wn * 32 + r8 + ((jj >> 1) << 3);
    const int rB1 = rB0 + 16;
    const int cB8 = jj & 1;
    const int rP  = r8 + ((jj & 1) << 3);
    const int cP8 = jj >> 1;

    float O[2][4][4];
#pragma unroll
    for (int x1 = 0; x1 < 2; x1++)
#pragma unroll
        for (int x2 = 0; x2 < 4; x2++)
#pragma unroll
            for (int x3 = 0; x3 < 4; x3++) { O[x1][x2][x3] = 0.f; }

    for (int c = 0; c < 16; c++) {
        // ======== QK: warp m32n32 over full 512-key chunk, 8 d-eighth stages ========
        float S[2][4][4];
#pragma unroll
        for (int mt = 0; mt < 2; mt++)
#pragma unroll
            for (int nt = 0; nt < 4; nt++)
#pragma unroll
                for (int t = 0; t < 4; t++) { S[mt][nt][t] = 0.f; }

        for (int dq = 0; dq < 8; dq++) {
            int g = c * 16 + dq;
            mbar_wait(mb + 8u * (uint32_t)(g & 1), (uint32_t)((g >> 1) & 1));
            __syncthreads();
            if (tid == 0) {
                int n = g + 1;
                uint32_t bar = mb + 8u * (uint32_t)(n & 1);
                mbar_expect(bar, 65536);
                bulkld(sb + SOFF + ((uint32_t)(n & 1) << 16), stage_src(n), 65536, bar);
            }
            uint32_t stg = sb + SOFF + ((uint32_t)(g & 1) << 16);

#pragma unroll
            for (int ks = 0; ks < 4; ks++) {
                int cq = dq * 8 + ks * 2 + cA8;
                uint32_t a00, a01, a02, a03, a10, a11, a12, a13;
                ldm4(a00, a01, a02, a03, sb + (uint32_t)(rA0 * 1024 + ((cq ^ (rA0 & 7)) << 4)));
                ldm4(a10, a11, a12, a13, sb + (uint32_t)(rA1 * 1024 + ((cq ^ (rA1 & 7)) << 4)));
                int ck = ks * 2 + cB8;
                uint32_t b0, b1, b2, b3;
                ldm4(b0, b1, b2, b3, stg + (uint32_t)(rB0 * 128 + ((ck ^ (rB0 & 7)) << 4)));
                mmab(S[0][0][0], S[0][0][1], S[0][0][2], S[0][0][3], a00, a01, a02, a03, b0, b1);
                mmab(S[0][1][0], S[0][1][1], S[0][1][2], S[0][1][3], a00, a01, a02, a03, b2, b3);
                mmab(S[1][0][0], S[1][0][1], S[1][0][2], S[1][0][3], a10, a11, a12, a13, b0, b1);
                mmab(S[1][1][0], S[1][1][1], S[1][1][2], S[1][1][3], a10, a11, a12, a13, b2, b3);
                ldm4(b0, b1, b2, b3, stg + (uint32_t)(rB1 * 128 + ((ck ^ (rB1 & 7)) << 4)));
                mmab(S[0][2][0], S[0][2][1], S[0][2][2], S[0][2][3], a00, a01, a02, a03, b0, b1);
                mmab(S[0][3][0], S[0][3][1], S[0][3][2], S[0][3][3], a00, a01, a02, a03, b2, b3);
                mmab(S[1][2][0], S[1][2][1], S[1][2][2], S[1][2][3], a10, a11, a12, a13, b0, b1);
                mmab(S[1][3][0], S[1][3][1], S[1][3][2], S[1][3][3], a10, a11, a12, a13, b2, b3);
            }
        }
        // E1 = exp(S*SC) -> smem bf16, partial row sums
#pragma unroll
        for (int mt = 0; mt < 2; mt++) {
            float pr0 = 0.f, pr1 = 0.f;
            int rw0 = mt * 16 + gid;
            int rw1 = rw0 + 8;
#pragma unroll
            for (int nt = 0; nt < 4; nt++) {
                float e0 = __expf(S[mt][nt][0] * SC), e1 = __expf(S[mt][nt][1] * SC);
                float e2 = __expf(S[mt][nt][2] * SC), e3 = __expf(S[mt][nt][3] * SC);
                pr0 += e0 + e1; pr1 += e2 + e3;
                int key = wn * 32 + nt * 8 + tig * 2;
                *(__nv_bfloat162*)(sm + EOFF + rw0 * 1024 + (((key >> 3) ^ (rw0 & 7)) << 4) + ((key & 7) << 1)) = __floats2bfloat162_rn(e0, e1);
                *(__nv_bfloat162*)(sm + EOFF + rw1 * 1024 + (((key >> 3) ^ (rw1 & 7)) << 4) + ((key & 7) << 1)) = __floats2bfloat162_rn(e2, e3);
            }
            pr0 += __shfl_xor_sync(0xffffffffu, pr0, 1);
            pr0 += __shfl_xor_sync(0xffffffffu, pr0, 2);
            pr1 += __shfl_xor_sync(0xffffffffu, pr1, 1);
            pr1 += __shfl_xor_sync(0xffffffffu, pr1, 2);
            if (tig == 0) {
                srow[wn * 32 + rw0] += pr0;
                srow[wn * 32 + rw1] += pr1;
            }
        }
        __syncthreads();

        // ======== chunk softmax -> E2 in place, Z accum, cls ========
        {
            int row = tid >> 4;
            int seg = tid & 15;
            float s = 0.f;
#pragma unroll
            for (int g2 = 0; g2 < 16; g2++) { s += srow[g2 * 32 + row]; }
            float rinv = 1.f / s;
            float z = 0.f;
#pragma unroll
            for (int i = 0; i < 4; i++) {
                int c16 = seg * 4 + i;
                uint32_t* p = (uint32_t*)(sm + EOFF + row * 1024 + ((c16 ^ (row & 7)) << 4));
#pragma unroll
                for (int qq = 0; qq < 4; qq++) {
                    float2 fv = __bfloat1622float2(*(__nv_bfloat162*)(p + qq));
                    float u0 = __expf(fv.x * rinv);
                    float u1 = __expf(fv.y * rinv);
                    z += u0 + u1;
                    *(__nv_bfloat162*)(p + qq) = __floats2bfloat162_rn(u0, u1);
                    if (blockIdx.x == 0 && row == 0) {
                        int col = c16 * 8 + qq * 2;
                        g_cls[c * 512 + col]     = u0;
                        g_cls[c * 512 + col + 1] = u1;
                    }
                }
            }
            z += __shfl_xor_sync(0xffffffffu, z, 1);
            z += __shfl_xor_sync(0xffffffffu, z, 2);
            z += __shfl_xor_sync(0xffffffffu, z, 4);
            z += __shfl_xor_sync(0xffffffffu, z, 8);
            if (seg == 0) Zb[row] += z;
        }

        // ======== PV: 8 stages of 64 keys x full d, warp m32n32 ========
        for (int kv = 0; kv < 8; kv++) {
            int g = c * 16 + 8 + kv;
            mbar_wait(mb + 8u * (uint32_t)(g & 1), (uint32_t)((g >> 1) & 1));
            __syncthreads();
            if (kv == 0) srow[tid] = 0.f;
            if (tid == 0 && g + 1 < 256) {
                int n = g + 1;
                uint32_t bar = mb + 8u * (uint32_t)(n & 1);
                mbar_expect(bar, 65536);
                bulkld(sb + SOFF + ((uint32_t)(n & 1) << 16), stage_src(n), 65536, bar);
            }
            uint32_t stg = sb + SOFF + ((uint32_t)(g & 1) << 16);
#pragma unroll
            for (int ks = 0; ks < 4; ks++) {
                uint32_t a00, a01, a02, a03, a10, a11, a12, a13;
                int ce  = kv * 8 + ks * 2 + cP8;
                int ra1 = 16 + rP;
                ldm4(a00, a01, a02, a03, sb + (uint32_t)(EOFF + rP  * 1024 + ((ce ^ (rP  & 7)) << 4)));
                ldm4(a10, a11, a12, a13, sb + (uint32_t)(EOFF + ra1 * 1024 + ((ce ^ (ra1 & 7)) << 4)));
                int rv = ks * 16 + rP;
#pragma unroll
                for (int nt2 = 0; nt2 < 2; nt2++) {
                    uint32_t b0, b1, b2, b3;
                    int cv = wn * 4 + nt2 * 2 + cP8;
                    ldm4t(b0, b1, b2, b3, stg + (uint32_t)(rv * 1024 + ((cv ^ (rv & 7)) << 4)));
                    mmab(O[0][2*nt2  ][0], O[0][2*nt2  ][1], O[0][2*nt2  ][2], O[0][2*nt2  ][3], a00, a01, a02, a03, b0, b1);
                    mmab(O[0][2*nt2+1][0], O[0][2*nt2+1][1], O[0][2*nt2+1][2], O[0][2*nt2+1][3], a00, a01, a02, a03, b2, b3);
                    mmab(O[1][2*nt2  ][0], O[1][2*nt2  ][1], O[1][2*nt2  ][2], O[1][2*nt2  ][3], a10, a11, a12, a13, b0, b1);
                    mmab(O[1][2*nt2+1][0], O[1][2*nt2+1][1], O[1][2*nt2+1][2], O[1][2*nt2+1][3], a10, a11, a12, a13, b2, b3);
                }
            }
        }
    }
    __syncthreads();

    // normalize + store bf16
#pragma unroll
    for (int mt = 0; mt < 2; mt++) {
        int r0 = mt * 16 + gid;
        float z0 = 1.f / Zb[r0];
        float z1 = 1.f / Zb[r0 + 8];
#pragma unroll
        for (int nt = 0; nt < 4; nt++) {
            int col = wn * 32 + nt * 8 + tig * 2;
            *(__nv_bfloat162*)&g_ab[(size_t)(q0 + r0) * DMOD + col]     = __floats2bfloat162_rn(O[mt][nt][0] * z0, O[mt][nt][1] * z0);
            *(__nv_bfloat162*)&g_ab[(size_t)(q0 + r0 + 8) * DMOD + col] = __floats2bfloat162_rn(O[mt][nt][2] * z1, O[mt][nt][3] * z1);
        }
    }
    if (blockIdx.x == 0 && tid == 0) g_Z0 = Zb[0];
}

// ---- stage-block layout addressing (must match attn2's smem expectations) ----
__device__ __forceinline__ size_t kstage_off(int row, int col)
{
    int blk = ((row >> 9) << 3) + (col >> 6);
    int r   = row & 511;
    int c16 = (col >> 3) & 7;
    int b8  = col & 7;
    return (size_t)blk * 65536 + (size_t)(r * 128 + ((c16 ^ (r & 7)) << 4) + b8 * 2);
}
__device__ __forceinline__ size_t vstage_off(int row, int col)
{
    int blk = ((row >> 9) << 3) + ((row >> 6) & 7);
    int r   = row & 63;
    int c16 = col >> 3;
    int b8  = col & 7;
    return (size_t)blk * 65536 + (size_t)(r * 1024 + ((c16 ^ (r & 7)) << 4) + b8 * 2);
}

// ---------------- bf16 tensor-core QKV projection GEMM ----------------
// blockIdx.z: 0 -> Q (row-major), 1 -> K (K-stage layout), 2 -> V (V-stage layout)
__global__ __launch_bounds__(256)
void gemm_qkv(const __nv_bfloat16* __restrict__ A,
              const __nv_bfloat16* __restrict__ Wa, const __nv_bfloat16* __restrict__ Wb2, const __nv_bfloat16* __restrict__ Wc,
              const float* __restrict__ ba, const float* __restrict__ bb2, const float* __restrict__ bc,
              __nv_bfloat16* __restrict__ oa, __nv_bfloat16* __restrict__ ob, __nv_bfloat16* __restrict__ oc)
{
    extern __shared__ char smg[];
    uint32_t sb = (uint32_t)__cvta_generic_to_shared(smg);

    const __nv_bfloat16* W;
    const float* bias;
    __nv_bfloat16* out;
    const int mode = blockIdx.z;
    if (mode == 0)      { W = Wa;  bias = ba;  out = oa; }
    else if (mode == 1) { W = Wb2; bias = bb2; out = ob; }
    else                { W = Wc;  bias = bc;  out = oc; }

    const int tid  = threadIdx.x;
    const int wd   = tid >> 5;
    const int lane = tid & 31;
    const int r8   = lane & 7;
    const int jj   = lane >> 3;
    const int gid  = lane >> 2;
    const int tig  = lane & 3;
    const int wm   = wd >> 2;
    const int wn   = wd & 3;
    const int bm   = blockIdx.x * 128;
    const int bn   = blockIdx.y * 128;
    const int rP   = r8 + ((jj & 1) << 3);
    const int cP8  = jj >> 1;

    float acc[4][4][4];
#pragma unroll
    for (int mt = 0; mt < 4; mt++)
#pragma unroll
        for (int nt = 0; nt < 4; nt++)
#pragma unroll
            for (int q2 = 0; q2 < 4; q2++) { acc[mt][nt][q2] = 0.f; }

#pragma unroll
    for (int i = 0; i < 4; i++) {
        int idx = i * 256 + tid;
        int row = idx >> 3;
        int c16 = idx & 7;
        cpa16(sb + (uint32_t)(row * 128 + ((c16 ^ (row & 7)) << 4)),
              (const char*)(A + (size_t)(bm + row) * DMOD) + (size_t)c16 * 16);
    }
#pragma unroll
    for (int i = 0; i < 4; i++) {
        int idx = i * 256 + tid;
        int k = idx >> 4;
        int c16 = idx & 15;
        cpa16(sb + (uint32_t)(32768 + k * 256 + ((c16 ^ (k & 7)) << 4)),
              (const char*)(W + (size_t)k * DMOD + bn) + (size_t)c16 * 16);
    }
    cpcommit();

    for (int s = 0; s < 8; s++) {
        cpwait0();
        __syncthreads();
        if (s < 7) {
            int ns = s + 1;
            uint32_t ab = sb + (uint32_t)((ns & 1) * 16384);
            uint32_t wb = sb + (uint32_t)(32768 + (ns & 1) * 16384);
#pragma unroll
            for (int i = 0; i < 4; i++) {
                int idx = i * 256 + tid;
                int row = idx >> 3;
                int c16 = idx & 7;
                cpa16(ab + (uint32_t)(row * 128 + ((c16 ^ (row & 7)) << 4)),
                      (const char*)(A + (size_t)(bm + row) * DMOD + (size_t)ns * 64) + (size_t)c16 * 16);
            }
#pragma unroll
            for (int i = 0; i < 4; i++) {
                int idx = i * 256 + tid;
                int k = idx >> 4;
                int c16 = idx & 15;
                cpa16(wb + (uint32_t)(k * 256 + ((c16 ^ (k & 7)) << 4)),
                      (const char*)(W + (size_t)(ns * 64 + k) * DMOD + bn) + (size_t)c16 * 16);
            }
            cpcommit();
        }
        uint32_t sa = sb + (uint32_t)((s & 1) * 16384);
        uint32_t sw = sb + (uint32_t)(32768 + (s & 1) * 16384);
#pragma unroll
        for (int ks = 0; ks < 4; ks++) {
            uint32_t am[4][4];
            int ck = ks * 2 + cP8;
#pragma unroll
            for (int mt = 0; mt < 4; mt++) {
                int rowA = wm * 64 + mt * 16 + rP;
                ldm4(am[mt][0], am[mt][1], am[mt][2], am[mt][3], sa + (uint32_t)(rowA * 128 + ((ck ^ (rowA & 7)) << 4)));
            }
#pragma unroll
            for (int nt2 = 0; nt2 < 2; nt2++) {
                uint32_t b0, b1, b2, b3;
                int rv = ks * 16 + rP;
                int cv = wn * 4 + nt2 * 2 + cP8;
                ldm4t(b0, b1, b2, b3, sw + (uint32_t)(rv * 256 + ((cv ^ (rv & 7)) << 4)));
#pragma unroll
                for (int mt = 0; mt < 4; mt++) {
                    mmab(acc[mt][2*nt2  ][0], acc[mt][2*nt2  ][1], acc[mt][2*nt2  ][2], acc[mt][2*nt2  ][3], am[mt][0], am[mt][1], am[mt][2], am[mt][3], b0, b1);
                    mmab(acc[mt][2*nt2+1][0], acc[mt][2*nt2+1][1], acc[mt][2*nt2+1][2], acc[mt][2*nt2+1][3], am[mt][0], am[mt][1], am[mt][2], am[mt][3], b2, b3);
                }
            }
        }
    }

#pragma unroll
    for (int mt = 0; mt < 4; mt++) {
        int row0 = bm + wm * 64 + mt * 16 + gid;
        int row1 = row0 + 8;
#pragma unroll
        for (int nt = 0; nt < 4; nt++) {
            int col = bn + wn * 32 + nt * 8 + tig * 2;
            float bx = bias[col];
            float by = bias[col + 1];
            __nv_bfloat162 v0 = __floats2bfloat162_rn(acc[mt][nt][0] + bx, acc[mt][nt][1] + by);
            __nv_bfloat162 v1 = __floats2bfloat162_rn(acc[mt][nt][2] + bx, acc[mt][nt][3] + by);
            if (mode == 0) {
                *(__nv_bfloat162*)&out[(size_t)row0 * DMOD + col] = v0;
                *(__nv_bfloat162*)&out[(size_t)row1 * DMOD + col] = v1;
            } else if (mode == 1) {
                *(__nv_bfloat162*)((char*)out + kstage_off(row0, col)) = v0;
                *(__nv_bfloat162*)((char*)out + kstage_off(row1, col)) = v1;
            } else {
                *(__nv_bfloat162*)((char*)out + vstage_off(row0, col)) = v0;
                *(__nv_bfloat162*)((char*)out + vstage_off(row1, col)) = v1;
            }
        }
    }
}

// ------------- bf16 output projection GEMM: out = A@W + bias + resid (fp32) -------------
__global__ __launch_bounds__(256)
void gemm_out(const __nv_bfloat16* __restrict__ A, const __nv_bfloat16* __restrict__ W,
              const float* __restrict__ bias, const float* __restrict__ resid,
              float* __restrict__ out)
{
    extern __shared__ char smg[];
    uint32_t sb = (uint32_t)__cvta_generic_to_shared(smg);

    const int tid  = threadIdx.x;
    const int wd   = tid >> 5;
    const int lane = tid & 31;
    const int r8   = lane & 7;
    const int jj   = lane >> 3;
    const int gid  = lane >> 2;
    const int tig  = lane & 3;
    const int wm   = wd >> 2;
    const int wn   = wd & 3;
    const int bm   = blockIdx.x * 128;
    const int bn   = blockIdx.y * 128;
    const int rP   = r8 + ((jj & 1) << 3);
    const int cP8  = jj >> 1;

    float acc[4][4][4];
#pragma unroll
    for (int mt = 0; mt < 4; mt++)
#pragma unroll
        for (int nt = 0; nt < 4; nt++)
#pragma unroll
            for (int q2 = 0; q2 < 4; q2++) { acc[mt][nt][q2] = 0.f; }

#pragma unroll
    for (int i = 0; i < 4; i++) {
        int idx = i * 256 + tid;
        int row = idx >> 3;
        int c16 = idx & 7;
        cpa16(sb + (uint32_t)(row * 128 + ((c16 ^ (row & 7)) << 4)),
              (const char*)(A + (size_t)(bm + row) * DMOD) + (size_t)c16 * 16);
    }
#pragma unroll
    for (int i = 0; i < 4; i++) {
        int idx = i * 256 + tid;
        int k = idx >> 4;
        int c16 = idx & 15;
        cpa16(sb + (uint32_t)(32768 + k * 256 + ((c16 ^ (k & 7)) << 4)),
              (const char*)(W + (size_t)k * DMOD + bn) + (size_t)c16 * 16);
    }
    cpcommit();

    for (int s = 0; s < 8; s++) {
        cpwait0();
        __syncthreads();
        if (s < 7) {
            int ns = s + 1;
            uint32_t ab = sb + (uint32_t)((ns & 1) * 16384);
            uint32_t wb = sb + (uint32_t)(32768 + (ns & 1) * 16384);
#pragma unroll
            for (int i = 0; i < 4; i++) {
                int idx = i * 256 + tid;
                int row = idx >> 3;
                int c16 = idx & 7;
                cpa16(ab + (uint32_t)(row * 128 + ((c16 ^ (row & 7)) << 4)),
                      (const char*)(A + (size_t)(bm + row) * DMOD + (size_t)ns * 64) + (size_t)c16 * 16);
            }
#pragma unroll
            for (int i = 0; i < 4; i++) {
                int idx = i * 256 + tid;
                int k = idx >> 4;
                int c16 = idx & 15;
                cpa16(wb + (uint32_t)(k * 256 + ((c16 ^ (k & 7)) << 4)),
                      (const char*)(W + (size_t)(ns * 64 + k) * DMOD + bn) + (size_t)c16 * 16);
            }
            cpcommit();
        }
        uint32_t sa = sb + (uint32_t)((s & 1) * 16384);
        uint32_t sw = sb + (uint32_t)(32768 + (s & 1) * 16384);
#pragma unroll
        for (int ks = 0; ks < 4; ks++) {
            uint32_t am[4][4];
            int ck = ks * 2 + cP8;
#pragma unroll
            for (int mt = 0; mt < 4; mt++) {
                int rowA = wm * 64 + mt * 16 + rP;
                ldm4(am[mt][0], am[mt][1], am[mt][2], am[mt][3], sa + (uint32_t)(rowA * 128 + ((ck ^ (rowA & 7)) << 4)));
            }
#pragma unroll
            for (int nt2 = 0; nt2 < 2; nt2++) {
                uint32_t b0, b1, b2, b3;
                int rv = ks * 16 + rP;
                int cv = wn * 4 + nt2 * 2 + cP8;
                ldm4t(b0, b1, b2, b3, sw + (uint32_t)(rv * 256 + ((cv ^ (rv & 7)) << 4)));
#pragma unroll
                for (int mt = 0; mt < 4; mt++) {
                    mmab(acc[mt][2*nt2  ][0], acc[mt][2*nt2  ][1], acc[mt][2*nt2  ][2], acc[mt][2*nt2  ][3], am[mt][0], am[mt][1], am[mt][2], am[mt][3], b0, b1);
                    mmab(acc[mt][2*nt2+1][0], acc[mt][2*nt2+1][1], acc[mt][2*nt2+1][2], acc[mt][2*nt2+1][3], am[mt][0], am[mt][1], am[mt][2], am[mt][3], b2, b3);
                }
            }
        }
    }

#pragma unroll
    for (int mt = 0; mt < 4; mt++) {
        int row0 = bm + wm * 64 + mt * 16 + gid;
        int row1 = row0 + 8;
#pragma unroll
        for (int nt = 0; nt < 4; nt++) {
            int col = bn + wn * 32 + nt * 8 + tig * 2;
            float bx = bias[col];
            float by = bias[col + 1];
            float2 ra = *(const float2*)&resid[(size_t)row0 * DMOD + col];
            float2 rb = *(const float2*)&resid[(size_t)row1 * DMOD + col];
            float2 v0 = make_float2(acc[mt][nt][0] + bx + ra.x, acc[mt][nt][1] + by + ra.y);
            float2 v1 = make_float2(acc[mt][nt][2] + bx + rb.x, acc[mt][nt][3] + by + rb.y);
            *(float2*)&out[(size_t)row0 * DMOD + col] = v0;
            *(float2*)&out[(size_t)row1 * DMOD + col] = v1;
        }
    }
}

__global__ void convf2b(const float* __restrict__ s, __nv_bfloat16* __restrict__ d, int n4)
{
    int i = blockIdx.x * blockDim.x + threadIdx.x;
    if (i < n4) {
        float4 v = ((const float4*)s)[i];
        ((__nv_bfloat162*)d)[2 * i]     = __floats2bfloat162_rn(v.x, v.y);
        ((__nv_bfloat162*)d)[2 * i + 1] = __floats2bfloat162_rn(v.z, v.w);
    }
}

__global__ void convw4(const float* __restrict__ Wq, const float* __restrict__ Wk,
                       const float* __restrict__ Wv, const float* __restrict__ Wo)
{
    int i = blockIdx.x * blockDim.x + threadIdx.x;
    int w = i >> 16;
    int j = i & 65535;
    const float* s;
    __nv_bfloat16* d;
    if (w == 0)      { s = Wq; d = g_w0; }
    else if (w == 1) { s = Wk; d = g_w1; }
    else if (w == 2) { s = Wv; d = g_w2; }
    else             { s = Wo; d = g_w3; }
    float4 v = ((const float4*)s)[j];
    ((__nv_bfloat162*)d)[2 * j]     = __floats2bfloat162_rn(v.x, v.y);
    ((__nv_bfloat162*)d)[2 * j + 1] = __floats2bfloat162_rn(v.z, v.w);
}

__global__ void cls_kernel(float* __restrict__ out)
{
    int m = blockIdx.x * 256 + threadIdx.x;
    out[m] = g_cls[m] / g_Z0;
}

extern "C" void kernel_launch(void* const* d_in, const int* in_sizes, int n_in,
                              void* d_out, int out_size)
{
    const float* x  = (const float*)d_in[0];
    const float* Wq = (const float*)d_in[1];
    const float* bq = (const float*)d_in[2];
    const float* Wk = (const float*)d_in[3];
    const float* bk = (const float*)d_in[4];
    const float* Wv = (const float*)d_in[5];
    const float* bv = (const float*)d_in[6];
    const float* Wo = (const float*)d_in[7];
    const float* bo = (const float*)d_in[8];
    float* out = (float*)d_out;

    __nv_bfloat16 *xb = 0, *w0 = 0, *w1 = 0, *w2 = 0, *w3 = 0, *qb = 0, *kb = 0, *vb = 0, *ab = 0;
    cudaGetSymbolAddress((void**)&xb, g_xb);
    cudaGetSymbolAddress((void**)&w0, g_w0);
    cudaGetSymbolAddress((void**)&w1, g_w1);
    cudaGetSymbolAddress((void**)&w2, g_w2);
    cudaGetSymbolAddress((void**)&w3, g_w3);
    cudaGetSymbolAddress((void**)&qb, g_qb);
    cudaGetSymbolAddress((void**)&kb, g_kb);
    cudaGetSymbolAddress((void**)&vb, g_vb);
    cudaGetSymbolAddress((void**)&ab, g_ab);

    cudaFuncSetAttribute(attn2, cudaFuncAttributeMaxDynamicSharedMemorySize, SM_TOTAL);
    cudaFuncSetAttribute(gemm_qkv, cudaFuncAttributeMaxDynamicSharedMemorySize, 65536);
    cudaFuncSetAttribute(gemm_out, cudaFuncAttributeMaxDynamicSharedMemorySize, 65536);

    convf2b<<<4096, 256>>>(x, xb, NTOK * DMOD / 4);
    convw4<<<1024, 256>>>(Wq, Wk, Wv, Wo);

    dim3 gq(64, 4, 3);
    gemm_qkv<<<gq, 256, 65536>>>(xb, w0, w1, w2, bq, bk, bv, qb, kb, vb);

    attn2<<<256, 512, SM_TOTAL>>>();

    dim3 gg(64, 4);
    gemm_out<<<gg, 256, 65536>>>(ab, w3, bo, x, out);
    cls_kernel<<<32, 256>>>(out + (size_t)NTOK * DMOD);
}